// round 3
// baseline (speedup 1.0000x reference)
#include <cuda_runtime.h>
#include <cuda_bf16.h>

// x: [B=32, C=256, W=56, H=56] fp32, contiguous.
// Groups of 4 consecutive channels. Keep elements that equal the group max AND are > 0,
// clamped to max_clamp; zero otherwise.
//
// Geometry in 256-bit (v8 = 8-float) units:
//   spatial plane per channel: 56*56 = 3136 floats = 392 v8 chunks
//   channel stride = 3136 floats
//   groups total = 32 * 64 = 2048
//   threads = 2048 * 392 = 802,816 = 3136 blocks x 256 (exact, no tail)
//
// Both streams use .cs (streaming / evict-first) hints: the read stream has zero
// reuse, so keeping it out of L2 leaves L2 capacity to buffer the dirty output
// stream and improves DRAM write-burst scheduling.

static constexpr int V8_PER_PLANE  = 392;    // 3136 / 8
static constexpr int FLT_PER_PLANE = 3136;
static constexpr int FLT_PER_GROUP = 4 * FLT_PER_PLANE;  // 12544
static constexpr int TOTAL_THREADS = 2048 * V8_PER_PLANE;

struct F8 { float v[8]; };

__device__ __forceinline__ F8 ldg256_cs(const float* p) {
    F8 r;
    asm volatile("ld.global.cs.v8.f32 {%0,%1,%2,%3,%4,%5,%6,%7}, [%8];"
                 : "=f"(r.v[0]), "=f"(r.v[1]), "=f"(r.v[2]), "=f"(r.v[3]),
                   "=f"(r.v[4]), "=f"(r.v[5]), "=f"(r.v[6]), "=f"(r.v[7])
                 : "l"(p));
    return r;
}

__device__ __forceinline__ void stg256_cs(float* p, const F8& r) {
    asm volatile("st.global.cs.v8.f32 [%0], {%1,%2,%3,%4,%5,%6,%7,%8};"
                 :: "l"(p),
                    "f"(r.v[0]), "f"(r.v[1]), "f"(r.v[2]), "f"(r.v[3]),
                    "f"(r.v[4]), "f"(r.v[5]), "f"(r.v[6]), "f"(r.v[7])
                 : "memory");
}

__global__ __launch_bounds__(256) void CGM_16707422781821_kernel(
    const float* __restrict__ x,
    float* __restrict__ out,
    const float* __restrict__ max_clamp_p)
{
    int idx = blockIdx.x * blockDim.x + threadIdx.x;

    const float mc = __ldg(max_clamp_p);

    // idx -> (group gb, spatial v8 chunk s)
    int gb = idx / V8_PER_PLANE;
    int s  = idx - gb * V8_PER_PLANE;
    long base = (long)gb * FLT_PER_GROUP + (long)s * 8;

    const float* xp = x + base;
    F8 c0 = ldg256_cs(xp);
    F8 c1 = ldg256_cs(xp + FLT_PER_PLANE);
    F8 c2 = ldg256_cs(xp + 2 * FLT_PER_PLANE);
    F8 c3 = ldg256_cs(xp + 3 * FLT_PER_PLANE);

    #pragma unroll
    for (int i = 0; i < 8; i++) {
        float m = fmaxf(fmaxf(c0.v[i], c1.v[i]), fmaxf(c2.v[i], c3.v[i]));
        float cl = fminf(m, mc);                    // clamp applies only to kept (max) entries
        bool pos = (m > 0.0f);
        c0.v[i] = (pos && c0.v[i] == m) ? cl : 0.0f;
        c1.v[i] = (pos && c1.v[i] == m) ? cl : 0.0f;
        c2.v[i] = (pos && c2.v[i] == m) ? cl : 0.0f;
        c3.v[i] = (pos && c3.v[i] == m) ? cl : 0.0f;
    }

    float* op = out + base;
    stg256_cs(op, c0);
    stg256_cs(op + FLT_PER_PLANE, c1);
    stg256_cs(op + 2 * FLT_PER_PLANE, c2);
    stg256_cs(op + 3 * FLT_PER_PLANE, c3);
}

extern "C" void kernel_launch(void* const* d_in, const int* in_sizes, int n_in,
                              void* d_out, int out_size) {
    const float* x = (const float*)d_in[0];
    // d_in[1] = group_size (int32, == 4, baked into geometry)
    const float* max_clamp_p = (const float*)d_in[2];
    float* out = (float*)d_out;

    const int threads = 256;
    const int blocks = TOTAL_THREADS / threads;  // 3136, exact
    CGM_16707422781821_kernel<<<blocks, threads>>>(x, out, max_clamp_p);
}

// round 4
// speedup vs baseline: 1.0571x; 1.0571x over previous
#include <cuda_runtime.h>
#include <cuda_bf16.h>

// x: [B=32, C=256, W=56, H=56] fp32, contiguous.
// Groups of 4 consecutive channels. Keep elements that equal the group max AND are > 0,
// clamped to max_clamp; zero otherwise.
//
// Geometry (float4 units):
//   spatial plane per channel: 56*56 = 3136 floats = 784 float4
//   one channel-group (4 channels) = 3136 float4, contiguous
//   groups total = 32 * 64 = 2048
//   threads = 2048 * 784 = 1,605,632; each reads 4x float4, writes 4x float4.
//
// Loads use .cs (evict-first: zero reuse on the read stream, keeps L2 capacity
// for buffering the dirty output stream). Stores use DEFAULT caching — R3 showed
// streaming stores regress DRAM throughput by ~20%.

static constexpr int F4_PER_PLANE = 784;
static constexpr int F4_PER_GROUP = 3136;
static constexpr int TOTAL_THREADS = 2048 * F4_PER_PLANE;  // 1,605,632

__device__ __forceinline__ float4 ldg_cs(const float4* p) {
    float4 r;
    asm volatile("ld.global.cs.v4.f32 {%0,%1,%2,%3}, [%4];"
                 : "=f"(r.x), "=f"(r.y), "=f"(r.z), "=f"(r.w)
                 : "l"(p));
    return r;
}

__global__ __launch_bounds__(256) void CGM_16707422781821_kernel(
    const float4* __restrict__ x,
    float4* __restrict__ out,
    const float* __restrict__ max_clamp_p)
{
    int idx = blockIdx.x * blockDim.x + threadIdx.x;
    if (idx >= TOTAL_THREADS) return;

    const float mc = __ldg(max_clamp_p);

    int gb = idx / F4_PER_PLANE;
    int s  = idx - gb * F4_PER_PLANE;
    long base = (long)gb * F4_PER_GROUP + s;

    float4 v0 = ldg_cs(x + base);
    float4 v1 = ldg_cs(x + base + F4_PER_PLANE);
    float4 v2 = ldg_cs(x + base + 2 * F4_PER_PLANE);
    float4 v3 = ldg_cs(x + base + 3 * F4_PER_PLANE);

    float mx_x = fmaxf(fmaxf(v0.x, v1.x), fmaxf(v2.x, v3.x));
    float mx_y = fmaxf(fmaxf(v0.y, v1.y), fmaxf(v2.y, v3.y));
    float mx_z = fmaxf(fmaxf(v0.z, v1.z), fmaxf(v2.z, v3.z));
    float mx_w = fmaxf(fmaxf(v0.w, v1.w), fmaxf(v2.w, v3.w));

    #define MASK1(v, m) (((v) == (m) && (v) > 0.0f) ? fminf((v), mc) : 0.0f)
    #define MASK4(v) do { \
        v.x = MASK1(v.x, mx_x); \
        v.y = MASK1(v.y, mx_y); \
        v.z = MASK1(v.z, mx_z); \
        v.w = MASK1(v.w, mx_w); \
    } while (0)

    MASK4(v0);
    MASK4(v1);
    MASK4(v2);
    MASK4(v3);

    out[base]                    = v0;   // default (cached) stores — L2 buffers the write stream
    out[base + F4_PER_PLANE]     = v1;
    out[base + 2 * F4_PER_PLANE] = v2;
    out[base + 3 * F4_PER_PLANE] = v3;

    #undef MASK4
    #undef MASK1
}

extern "C" void kernel_launch(void* const* d_in, const int* in_sizes, int n_in,
                              void* d_out, int out_size) {
    const float4* x = (const float4*)d_in[0];
    // d_in[1] = group_size (int32, == 4, baked into geometry)
    const float* max_clamp_p = (const float*)d_in[2];
    float4* out = (float4*)d_out;

    const int threads = 256;
    const int blocks = (TOTAL_THREADS + threads - 1) / threads;  // 6272
    CGM_16707422781821_kernel<<<blocks, threads>>>(x, out, max_clamp_p);
}

// round 6
// speedup vs baseline: 1.0580x; 1.0009x over previous
#include <cuda_runtime.h>
#include <cuda_bf16.h>

// x: [B=32, C=256, W=56, H=56] fp32, contiguous.
// Groups of 4 consecutive channels. Keep elements that equal the group max AND are > 0,
// clamped to max_clamp; zero otherwise.
//
// Geometry (float4 units):
//   spatial plane per channel: 3136 floats = 784 float4, split into two halves of 392.
//   Each thread handles one float4 slot in BOTH halves of its group's plane:
//     8 front-batched LDG.128 (4 channels x 2 halves), then masked, then 8 STG.128.
//   threads = 2048 groups * 392 = 802,816 = 3136 blocks x 256 (exact).
//   Lane-consecutive threads hit address-consecutive float4 within each half -> fully coalesced.

static constexpr int F4_PER_PLANE = 784;
static constexpr int HALF         = 392;
static constexpr int F4_PER_GROUP = 3136;
static constexpr int TOTAL_THREADS = 2048 * HALF;   // 802,816

__global__ __launch_bounds__(256) void CGM_16707422781821_kernel(
    const float4* __restrict__ x,
    float4* __restrict__ out,
    const float* __restrict__ max_clamp_p)
{
    int idx = blockIdx.x * blockDim.x + threadIdx.x;

    const float mc = __ldg(max_clamp_p);

    int gb = idx / HALF;              // group index (0..2047)
    int s  = idx - gb * HALF;         // slot within first half (0..391)
    long base = (long)gb * F4_PER_GROUP + s;

    const float4* xp = x + base;
    // Front-batched 8x LDG.128: 4 channels x 2 plane-halves.
    float4 a0 = xp[0];
    float4 a1 = xp[F4_PER_PLANE];
    float4 a2 = xp[2 * F4_PER_PLANE];
    float4 a3 = xp[3 * F4_PER_PLANE];
    float4 b0 = xp[HALF];
    float4 b1 = xp[HALF + F4_PER_PLANE];
    float4 b2 = xp[HALF + 2 * F4_PER_PLANE];
    float4 b3 = xp[HALF + 3 * F4_PER_PLANE];

    #define GMAX(c0,c1,c2,c3,f) fmaxf(fmaxf(c0.f, c1.f), fmaxf(c2.f, c3.f))
    #define MASK1(v, m) (((v) == (m) && (v) > 0.0f) ? fminf((v), mc) : 0.0f)
    #define DOGROUP(c0,c1,c2,c3) do { \
        float mx = GMAX(c0,c1,c2,c3,x); \
        float my = GMAX(c0,c1,c2,c3,y); \
        float mz = GMAX(c0,c1,c2,c3,z); \
        float mw = GMAX(c0,c1,c2,c3,w); \
        c0.x = MASK1(c0.x, mx); c0.y = MASK1(c0.y, my); c0.z = MASK1(c0.z, mz); c0.w = MASK1(c0.w, mw); \
        c1.x = MASK1(c1.x, mx); c1.y = MASK1(c1.y, my); c1.z = MASK1(c1.z, mz); c1.w = MASK1(c1.w, mw); \
        c2.x = MASK1(c2.x, mx); c2.y = MASK1(c2.y, my); c2.z = MASK1(c2.z, mz); c2.w = MASK1(c2.w, mw); \
        c3.x = MASK1(c3.x, mx); c3.y = MASK1(c3.y, my); c3.z = MASK1(c3.z, mz); c3.w = MASK1(c3.w, mw); \
    } while (0)

    DOGROUP(a0, a1, a2, a3);
    DOGROUP(b0, b1, b2, b3);

    float4* op = out + base;
    op[0]                        = a0;
    op[F4_PER_PLANE]             = a1;
    op[2 * F4_PER_PLANE]         = a2;
    op[3 * F4_PER_PLANE]         = a3;
    op[HALF]                     = b0;
    op[HALF + F4_PER_PLANE]      = b1;
    op[HALF + 2 * F4_PER_PLANE]  = b2;
    op[HALF + 3 * F4_PER_PLANE]  = b3;

    #undef DOGROUP
    #undef MASK1
    #undef GMAX
}

extern "C" void kernel_launch(void* const* d_in, const int* in_sizes, int n_in,
                              void* d_out, int out_size) {
    const float4* x = (const float4*)d_in[0];
    // d_in[1] = group_size (int32, == 4, baked into geometry)
    const float* max_clamp_p = (const float*)d_in[2];
    float4* out = (float4*)d_out;

    const int threads = 256;
    const int blocks = TOTAL_THREADS / threads;  // 3136, exact
    CGM_16707422781821_kernel<<<blocks, threads>>>(x, out, max_clamp_p);
}